// round 12
// baseline (speedup 1.0000x reference)
#include <cuda_runtime.h>
#include <stdint.h>
#include <math.h>

#define NTOT    (1<<22)
#define NBANDS  8
#define TPB     256

#define SC_CHUNK 2048
#define SC_NBLK  (NTOT/SC_CHUNK)   /* 2048 */
#define SC_L     (SC_CHUNK/TPB)    /* 8    */

#define R_CAP    540672             /* NTOT/8 + 16384 */

#define TILE     2048
#define PT       8                  /* TILE / TPB */
#define NTILE    (NTOT/TILE)        /* 2048 */
#define NWARP    (TPB/32)           /* 8 */

typedef unsigned long long ull;

// ---------------- static device scratch ----------------
__device__ ull      g_key[8*R_CAP];
__device__ ull      g_keyB[8*R_CAP];
__device__ int      g_bcnt[NBANDS*SC_NBLK];
__device__ int      g_boff[NBANDS*SC_NBLK];
__device__ int      g_cnt[NBANDS];
__device__ float    g_nt[NTOT], g_yy[NTOT];
__device__ unsigned g_dde[NTOT];            // diag bits with band in low 3 bits
__device__ float4   g_thrM[NTILE*TPB];      // per-thread exclusive in-tile matrices
__device__ double   g_blkM[NTILE*4], g_blkMex[NTILE*4];
__device__ double   g_bsum[NTILE];
__device__ float    g_amps[NBANDS], g_lags[NBANDS], g_ka, g_kc;

// affine lookback state
__device__ int    g_ticketA;
__device__ int    g_flagA[NTILE];
__device__ double g_tAagg[NTILE*2], g_tAinc[NTILE*2];

__device__ __forceinline__ unsigned fkey(float f){
    unsigned u = __float_as_uint(f);
    return (u & 0x80000000u) ? ~u : (u | 0x80000000u);
}
__device__ __forceinline__ float unfkey(unsigned k){
    unsigned u = (k & 0x80000000u) ? (k & 0x7fffffffu) : ~k;
    return __uint_as_float(u);
}

__device__ __forceinline__ void mmulD(double r[4], const double n[4], const double o[4]){
    double t0 = n[0]*o[0] + n[1]*o[2];
    double t1 = n[0]*o[1] + n[1]*o[3];
    double t2 = n[2]*o[0] + n[3]*o[2];
    double t3 = n[2]*o[1] + n[3]*o[3];
    double mx = fmax(fmax(fabs(t0),fabs(t1)), fmax(fabs(t2),fabs(t3)));
    double s  = (mx > 0.0) ? 1.0/mx : 1.0;
    r[0]=t0*s; r[1]=t1*s; r[2]=t2*s; r[3]=t3*s;
}

// ---------------- params / reset ----------------
__global__ void k_init(const float* __restrict__ lad, const float* __restrict__ lg,
                       const float* __restrict__ lkp){
    if (threadIdx.x == 0){
        g_amps[0] = 1.f; g_lags[0] = 0.f;
        for (int b = 1; b < NBANDS; b++){
            g_amps[b] = expf(lad[b-1]);
            g_lags[b] = lg[b-1];
        }
        g_ka = expf(lkp[0]);
        g_kc = expf(lkp[1]);
    }
}

__global__ void k_reset(){
    int i = blockIdx.x*blockDim.x + threadIdx.x;
    if (i < NTILE) g_flagA[i] = 0;
    if (i == 0) g_ticketA = 0;
}

// ---------------- stage 1: histogram (band-major) ----------------
__global__ void k_count(const int* __restrict__ band){
    __shared__ int sc[NBANDS];
    int tid = threadIdx.x;
    if (tid < NBANDS) sc[tid] = 0;
    __syncthreads();
    int cnt[NBANDS];
    #pragma unroll
    for (int b = 0; b < NBANDS; b++) cnt[b] = 0;
    int base = blockIdx.x * SC_CHUNK;
    for (int k = tid; k < SC_CHUNK; k += TPB) cnt[band[base+k]]++;
    #pragma unroll
    for (int b = 0; b < NBANDS; b++) if (cnt[b]) atomicAdd(&sc[b], cnt[b]);
    __syncthreads();
    if (tid < NBANDS) g_bcnt[tid*SC_NBLK + blockIdx.x] = sc[tid];
}

// ---------------- stage 1b: 8 independent per-band scans ----------------
__global__ void k_offsets8(){
    __shared__ int ssum[TPB];
    int b = blockIdx.x;
    int tid = threadIdx.x;
    int v[SC_NBLK/TPB];
    int run = 0;
    #pragma unroll
    for (int q = 0; q < SC_NBLK/TPB; q++){
        v[q] = run;
        run += g_bcnt[b*SC_NBLK + tid*(SC_NBLK/TPB) + q];
    }
    ssum[tid] = run;
    __syncthreads();
    for (int off = 1; off < TPB; off <<= 1){
        int pv = (tid >= off) ? ssum[tid-off] : 0;
        __syncthreads();
        ssum[tid] += pv;
        __syncthreads();
    }
    int excl = tid ? ssum[tid-1] : 0;
    #pragma unroll
    for (int q = 0; q < SC_NBLK/TPB; q++)
        g_boff[b*SC_NBLK + tid*(SC_NBLK/TPB) + q] = excl + v[q];
    if (tid == TPB-1) g_cnt[b] = excl + run;
}

// ---------------- stage 2: stable partition into band regions ----------------
__global__ void k_scatter(const float* __restrict__ t, const int* __restrict__ band){
    __shared__ float s_t[SC_CHUNK];
    __shared__ int   s_b[SC_CHUNK];
    __shared__ int   s_scan[NBANDS*TPB];
    __shared__ float s_lag[NBANDS];
    int tid = threadIdx.x;
    int base = blockIdx.x * SC_CHUNK;
    if (tid < NBANDS) s_lag[tid] = g_lags[tid];
    for (int k = tid; k < SC_CHUNK; k += TPB){
        s_t[k] = t[base+k]; s_b[k] = band[base+k];
    }
    __syncthreads();
    int cnt[NBANDS];
    #pragma unroll
    for (int b = 0; b < NBANDS; b++) cnt[b] = 0;
    #pragma unroll
    for (int j = 0; j < SC_L; j++) cnt[s_b[tid*SC_L + j]]++;
    #pragma unroll
    for (int b = 0; b < NBANDS; b++) s_scan[b*TPB + tid] = cnt[b];
    __syncthreads();
    for (int off = 1; off < TPB; off <<= 1){
        int v[NBANDS];
        #pragma unroll
        for (int b = 0; b < NBANDS; b++) v[b] = (tid >= off) ? s_scan[b*TPB + tid - off] : 0;
        __syncthreads();
        #pragma unroll
        for (int b = 0; b < NBANDS; b++) s_scan[b*TPB + tid] += v[b];
        __syncthreads();
    }
    int pos[NBANDS];
    #pragma unroll
    for (int b = 0; b < NBANDS; b++)
        pos[b] = b*R_CAP + g_boff[b*SC_NBLK + blockIdx.x] + (tid ? s_scan[b*TPB + tid - 1] : 0);
    #pragma unroll
    for (int j = 0; j < SC_L; j++){
        int li = tid*SC_L + j;
        int b = s_b[li];
        float nt = s_t[li] - s_lag[b];
        ull key = ((ull)fkey(nt) << 32) | ((ull)(unsigned)(base + li) << 3) | (unsigned)b;
        g_key[pos[b]++] = key;
    }
}

// ---------------- merge-path helpers ----------------
__device__ __forceinline__ int diag_g(const ull* __restrict__ A, int la,
                                      const ull* __restrict__ B, int lb, int k){
    int lo = k - lb; if (lo < 0) lo = 0;
    int hi = k < la ? k : la;
    while (lo < hi){
        int mid = (lo + hi) >> 1;
        if (__ldg(&A[mid]) < __ldg(&B[k-mid-1])) lo = mid + 1; else hi = mid;
    }
    return lo;
}

__global__ void k_mergeL(int level){
    __shared__ ull sbuf[TILE];
    __shared__ int s_i0, s_i1;
    int p = blockIdx.y;

    const ull* src; ull* dst;
    int aS, bS, dS, la, lb;
    if (level == 0){
        src = g_key; dst = g_keyB;
        aS = (2*p)*R_CAP;   la = g_cnt[2*p];
        bS = (2*p+1)*R_CAP; lb = g_cnt[2*p+1];
        dS = (2*p)*R_CAP;
    } else {
        src = g_keyB; dst = g_key;
        aS = (4*p)*R_CAP;   la = g_cnt[4*p]   + g_cnt[4*p+1];
        bS = (4*p+2)*R_CAP; lb = g_cnt[4*p+2] + g_cnt[4*p+3];
        dS = (4*p)*R_CAP;
    }
    int psize = la + lb;
    int t0 = blockIdx.x * TILE;
    if (t0 >= psize) return;
    int t1 = t0 + TILE; if (t1 > psize) t1 = psize;
    int tsz = t1 - t0;

    const ull* A = src + aS;
    const ull* B = src + bS;

    if (threadIdx.x == 0)  s_i0 = diag_g(A, la, B, lb, t0);
    if (threadIdx.x == 32) s_i1 = diag_g(A, la, B, lb, t1);
    __syncthreads();
    int i0 = s_i0, i1 = s_i1;
    int j0 = t0 - i0;
    int ai = i1 - i0;
    int bj = tsz - ai;

    for (int k = threadIdx.x; k < tsz; k += TPB)
        sbuf[k] = (k < ai) ? A[i0 + k] : B[j0 + k - ai];
    __syncthreads();

    int kloc = threadIdx.x * PT;
    int n = tsz - kloc; if (n > PT) n = PT; if (n < 0) n = 0;
    ull out[PT];
    if (n > 0){
        int lo = kloc - bj; if (lo < 0) lo = 0;
        int hi = kloc < ai ? kloc : ai;
        while (lo < hi){
            int mid = (lo + hi) >> 1;
            if (sbuf[mid] < sbuf[ai + kloc - mid - 1]) lo = mid + 1; else hi = mid;
        }
        int i = lo, j = kloc - lo;
        #pragma unroll
        for (int q = 0; q < PT; q++){
            if (q < n){
                bool ta = (j >= bj) || (i < ai && sbuf[i] < sbuf[ai + j]);
                out[q] = ta ? sbuf[i++] : sbuf[ai + j++];
            }
        }
    }
    // direct contiguous register writes (64B per thread)
    ull* D = dst + dS + t0 + kloc;
    #pragma unroll
    for (int q = 0; q < PT; q++) if (q < n) D[q] = out[q];
}

// ---------------- stage 3: final merge + gather + fp64 warp-shuffle matrix scan ----------------
__global__ void __launch_bounds__(TPB)
k_mgsr(const float* __restrict__ y, const float* __restrict__ dg){
    __shared__ __align__(16) char raw[TILE*12];   // phase1: ull sbuf (16KB); phase2: 3 arrays (24KB)
    ull*      sbuf  = (ull*)raw;
    float*    s_nt  = (float*)raw;
    float*    s_y   = (float*)(raw + TILE*4);
    unsigned* s_de  = (unsigned*)(raw + TILE*8);
    __shared__ ull    lastk[TPB];
    __shared__ double sWin[NWARP][4];
    __shared__ float  sam[NBANDS];
    __shared__ int    s_i0, s_i1;
    const unsigned FULL = 0xFFFFFFFFu;

    int tid = threadIdx.x;
    int lane = tid & 31;
    int wid  = tid >> 5;
    if (tid < NBANDS) sam[tid] = g_amps[tid];
    __syncthreads();
    int t0 = blockIdx.x * TILE;

    // final 2-list merge
    int la = g_cnt[0] + g_cnt[1] + g_cnt[2] + g_cnt[3];
    int lb = NTOT - la;
    const ull* A = g_key;
    const ull* B = g_key + 4*R_CAP;
    if (tid == 0)  s_i0 = diag_g(A, la, B, lb, t0);
    if (tid == 32) s_i1 = diag_g(A, la, B, lb, t0 + TILE);
    __syncthreads();
    int i0 = s_i0, i1 = s_i1, j0 = t0 - i0;
    int ai = i1 - i0, bj = TILE - ai;
    ull kprev = 0;
    if (t0 > 0){
        ull ca = (i0 > 0) ? __ldg(&A[i0-1]) : 0ULL;
        ull cb = (j0 > 0) ? __ldg(&B[j0-1]) : 0ULL;
        kprev = ca > cb ? ca : cb;
    }
    for (int k = tid; k < TILE; k += TPB)
        sbuf[k] = (k < ai) ? A[i0 + k] : B[j0 + k - ai];
    __syncthreads();

    int kloc = tid * PT;
    int lo = kloc - bj; if (lo < 0) lo = 0;
    int hi = kloc < ai ? kloc : ai;
    while (lo < hi){
        int mid = (lo + hi) >> 1;
        if (sbuf[mid] < sbuf[ai + kloc - mid - 1]) lo = mid + 1; else hi = mid;
    }
    int ii = lo, jj = kloc - lo;
    ull out[PT];
    #pragma unroll
    for (int q = 0; q < PT; q++){
        bool ta = (jj >= bj) || (ii < ai && sbuf[ii] < sbuf[ai + jj]);
        out[q] = ta ? sbuf[ii++] : sbuf[ai + jj++];
    }
    lastk[tid] = out[PT-1];
    __syncthreads();   // all sbuf reads done; lastk visible; raw reusable
    ull pk = (tid == 0) ? (t0 ? kprev : out[0]) : lastk[tid-1];
    float tprev0 = unfkey((unsigned)(pk >> 32));

    // decode + gather into smem
    #pragma unroll
    for (int q = 0; q < PT; q++){
        ull kk = out[q];
        int  idx = (int)((kk >> 3) & 0x3FFFFFu);
        unsigned db = __float_as_uint(__ldg(&dg[idx]));
        s_nt[kloc+q] = unfkey((unsigned)(kk >> 32));
        s_y [kloc+q] = __ldg(&y[idx]);
        s_de[kloc+q] = (db & ~7u) | (unsigned)(kk & 7u);
    }
    // per-thread Mobius matrix over segment (fp32 — validated)
    float a = g_ka, c = g_kc;
    float m0=1.f, m1=0.f, m2=0.f, m3=1.f;
    {
        float tprev = tprev0;
        #pragma unroll
        for (int q = 0; q < PT; q++){
            float nt = s_nt[kloc+q];
            unsigned enc = s_de[kloc+q];
            float dd = __uint_as_float(enc & ~7u);
            float amp = sam[enc & 7u];
            float dt = nt - tprev; tprev = nt;
            float phi2 = expf(-2.f*c*dt);
            float V = amp, U = a*amp;
            float Am = dd + U*V;
            float e00 = (Am - 2.f*U*V)*phi2, e01 = V*V, e10 = -U*U*phi2, e11 = Am;
            float r0 = e00*m0 + e01*m2, r1 = e00*m1 + e01*m3;
            float r2 = e10*m0 + e11*m2, r3 = e10*m1 + e11*m3;
            float mx = fmaxf(fmaxf(fabsf(r0),fabsf(r1)), fmaxf(fabsf(r2),fabsf(r3)));
            float sc = (mx > 0.f) ? 1.f/mx : 1.f;
            m0=r0*sc; m1=r1*sc; m2=r2*sc; m3=r3*sc;
        }
    }
    // warp-level inclusive scan in FP64 (shuffle; ill-conditioned matrices need fp64)
    double W[4] = {(double)m0,(double)m1,(double)m2,(double)m3};
    #pragma unroll
    for (int d = 1; d < 32; d <<= 1){
        double Q[4];
        #pragma unroll
        for (int q = 0; q < 4; q++) Q[q] = __shfl_up_sync(FULL, W[q], d);
        if (lane >= d){ double R[4]; mmulD(R, W, Q); W[0]=R[0]; W[1]=R[1]; W[2]=R[2]; W[3]=R[3]; }
    }
    if (lane == 31){
        sWin[wid][0]=W[0]; sWin[wid][1]=W[1]; sWin[wid][2]=W[2]; sWin[wid][3]=W[3];
    }
    __syncthreads();
    // cross-warp serial inclusive (one thread, 8 fp64 composes)
    if (tid == 0){
        double run[4] = {sWin[0][0], sWin[0][1], sWin[0][2], sWin[0][3]};
        for (int w = 1; w < NWARP; w++){
            double cu[4] = {sWin[w][0], sWin[w][1], sWin[w][2], sWin[w][3]};
            double r[4]; mmulD(r, cu, run);
            for (int q=0;q<4;q++){ run[q]=r[q]; sWin[w][q]=r[q]; }
        }
        for (int q=0;q<4;q++) g_blkM[blockIdx.x*4+q] = sWin[NWARP-1][q];
    }
    __syncthreads();
    // per-thread exclusive block matrix (fp64)
    {
        double Pd[4];
        #pragma unroll
        for (int q = 0; q < 4; q++) Pd[q] = __shfl_up_sync(FULL, W[q], 1);
        if (lane == 0){ Pd[0]=1.0; Pd[1]=0.0; Pd[2]=0.0; Pd[3]=1.0; }
        double Wd[4];
        if (wid == 0){ Wd[0]=1.0; Wd[1]=0.0; Wd[2]=0.0; Wd[3]=1.0; }
        else { for (int q=0;q<4;q++) Wd[q] = sWin[wid-1][q]; }
        double Ex[4]; mmulD(Ex, Pd, Wd);
        g_thrM[blockIdx.x*TPB + tid] =
            make_float4((float)Ex[0],(float)Ex[1],(float)Ex[2],(float)Ex[3]);
    }

    // coalesced writes of compact sorted arrays
    for (int k = tid; k < TILE; k += TPB){
        g_nt [t0+k] = s_nt[k];
        g_yy [t0+k] = s_y [k];
        g_dde[t0+k] = s_de[k];
    }
}

// ---------------- tile-matrix exclusive scan (fp64 warp shuffles) ----------------
__global__ void k_blkscanM(){
    __shared__ double sW[32][4];
    const unsigned FULL = 0xFFFFFFFFu;
    int tid = threadIdx.x;
    int lane = tid & 31;
    int wid  = tid >> 5;

    double p0[4], m[4], S[4];
    for (int q=0;q<4;q++) p0[q] = g_blkM[(tid*2+0)*4+q];
    for (int q=0;q<4;q++) m[q]  = g_blkM[(tid*2+1)*4+q];
    mmulD(S, m, p0);   // inclusive of my pair

    #pragma unroll
    for (int d = 1; d < 32; d <<= 1){
        double Q[4];
        #pragma unroll
        for (int q=0;q<4;q++) Q[q] = __shfl_up_sync(FULL, S[q], d);
        if (lane >= d){ double R[4]; mmulD(R, S, Q); for (int q=0;q<4;q++) S[q]=R[q]; }
    }
    if (lane == 31){ for (int q=0;q<4;q++) sW[wid][q] = S[q]; }
    __syncthreads();
    if (tid == 0){
        double run[4] = {sW[0][0], sW[0][1], sW[0][2], sW[0][3]};
        for (int w = 1; w < 32; w++){
            double cu[4] = {sW[w][0], sW[w][1], sW[w][2], sW[w][3]};
            double r[4]; mmulD(r, cu, run);
            for (int q=0;q<4;q++){ run[q]=r[q]; sW[w][q]=r[q]; }
        }
    }
    __syncthreads();

    double Sp[4];
    #pragma unroll
    for (int q=0;q<4;q++) Sp[q] = __shfl_up_sync(FULL, S[q], 1);
    if (lane == 0){ Sp[0]=1.0; Sp[1]=0.0; Sp[2]=0.0; Sp[3]=1.0; }
    double Wd[4];
    if (wid == 0){ Wd[0]=1.0; Wd[1]=0.0; Wd[2]=0.0; Wd[3]=1.0; }
    else { for (int q=0;q<4;q++) Wd[q] = sW[wid-1][q]; }

    double Ex0[4]; mmulD(Ex0, Sp, Wd);
    for (int q=0;q<4;q++) g_blkMex[(tid*2+0)*4+q] = Ex0[q];
    double Ex1[4]; mmulD(Ex1, p0, Ex0);
    for (int q=0;q<4;q++) g_blkMex[(tid*2+1)*4+q] = Ex1[q];
}

// ---------------- affine lookback (2 doubles, proven) ----------------
__device__ __forceinline__ void lookbackA(int tile, int lane, double aga, double agb,
                                          double* Pa, double* Pb){
    const unsigned FULL = 0xFFFFFFFFu;
    if (tile == 0){
        *Pa = 1.0; *Pb = 0.0;
        if (lane == 0){
            volatile double* vi = g_tAinc;
            vi[0] = aga; vi[1] = agb;
            __threadfence();
            atomicExch(&g_flagA[0], 2);
        }
        return;
    }
    if (lane == 0){
        volatile double* va = g_tAagg;
        va[tile*2] = aga; va[tile*2+1] = agb;
        __threadfence();
        atomicExch(&g_flagA[tile], 1);
    }
    __syncwarp(FULL);
    double Ra = 1.0, Rb = 0.0;
    int base = tile;
    while (true){
        int j = base - 1 - lane;
        int f = 0;
        if (j >= 0){
            volatile int* vf = g_flagA;
            do { f = vf[j]; } while (f == 0);
        }
        __threadfence();
        double Ma = 1.0, Mb = 0.0;
        if (j >= 0){
            volatile double* src = (f == 2) ? g_tAinc : g_tAagg;
            Ma = src[j*2]; Mb = src[j*2+1];
        }
        unsigned m2 = __ballot_sync(FULL, (j >= 0) && (f == 2));
        int lstar = m2 ? (__ffs(m2) - 1) : 32;
        double Sa = Ma, Sb = Mb;
        #pragma unroll
        for (int d = 1; d < 32; d <<= 1){
            double Qa = __shfl_up_sync(FULL, Sa, d);
            double Qb = __shfl_up_sync(FULL, Sb, d);
            if (lane >= d){ Sb = Qa*Sb + Qb; Sa = Qa*Sa; }
        }
        if (lstar < 32){
            double Wa = __shfl_sync(FULL, Sa, lstar);
            double Wb = __shfl_sync(FULL, Sb, lstar);
            *Pa = Ra*Wa; *Pb = Ra*Wb + Rb;
            break;
        } else {
            double Wa = __shfl_sync(FULL, Sa, 31);
            double Wb = __shfl_sync(FULL, Sb, 31);
            Rb = Ra*Wb + Rb; Ra = Ra*Wa;
            base -= 32;
        }
    }
    if (lane == 0){
        double ia = aga * (*Pa);
        double ib = aga * (*Pb) + agb;
        volatile double* vi = g_tAinc;
        vi[tile*2] = ia; vi[tile*2+1] = ib;
        __threadfence();
        atomicExch(&g_flagA[tile], 2);
    }
}

// ---------------- stage 4: S prefix (from thrM) + f lookback + likelihood ----------------
__global__ void __launch_bounds__(TPB)
k_apply(){
    __shared__ __align__(16) char raw[TILE*12];
    float*    s_nt = (float*)raw;
    float*    s_y  = (float*)(raw + TILE*4);
    unsigned* s_de = (unsigned*)(raw + TILE*8);
    __shared__ double sA[NWARP][2];
    __shared__ double sred[TPB];
    __shared__ double sP[2];
    __shared__ float  s_pv;
    __shared__ float  sam[NBANDS];
    __shared__ int    s_tile;
    const unsigned FULL = 0xFFFFFFFFu;

    int tid = threadIdx.x;
    int lane = tid & 31;
    int wid  = tid >> 5;
    if (tid == 0) s_tile = atomicAdd(&g_ticketA, 1);
    if (tid < NBANDS) sam[tid] = g_amps[tid];
    __syncthreads();
    int tile = s_tile;
    int t0 = tile * TILE;

    float pvg = 0.f;
    if (tid == 0 && t0 > 0) pvg = g_nt[t0-1];
    for (int k = tid; k < TILE; k += TPB){
        s_nt[k] = g_nt [t0+k];
        s_y [k] = g_yy [t0+k];
        s_de[k] = g_dde[t0+k];
    }
    __syncthreads();
    if (tid == 0) s_pv = (t0 > 0) ? pvg : s_nt[0];
    __syncthreads();

    float4 mf = g_thrM[tile*TPB + tid];
    double Pt[4] = {(double)mf.x,(double)mf.y,(double)mf.z,(double)mf.w};
    double Pb4[4]; for (int q=0;q<4;q++) Pb4[q] = g_blkMex[tile*4+q];
    double E[4]; mmulD(E, Pt, Pb4);
    float Sp0 = (float)(E[1] / E[3]);

    int kloc = tid * PT;
    float tprev0 = kloc ? s_nt[kloc-1] : s_pv;
    float a = g_ka, c = g_kc;

    // f-affine per thread
    double Sa, Sb;
    {
        float Sp = Sp0;
        float al = 1.f, be = 0.f;
        float tprev = tprev0;
        #pragma unroll
        for (int q = 0; q < PT; q++){
            float nt = s_nt[kloc+q];
            unsigned enc = s_de[kloc+q];
            float dd = __uint_as_float(enc & ~7u);
            float amp = sam[enc & 7u];
            float dt = nt - tprev; tprev = nt;
            float phi = expf(-c*dt);
            float phi2 = phi*phi;
            float V = amp, U = a*V;
            float Am = dd + U*V;
            float S = phi2 * Sp;
            float D = Am - U*U*S;
            float W = (V - U*S) / D;
            float an = phi * (1.f - W*U);
            float bn = W * s_y[kloc+q];
            be = an*be + bn;
            al *= an;
            Sp = S + D*W*W;
        }
        Sa = (double)al; Sb = (double)be;
    }
    // warp inclusive scan (fp64 shuffles)
    #pragma unroll
    for (int d = 1; d < 32; d <<= 1){
        double Qa = __shfl_up_sync(FULL, Sa, d);
        double Qb = __shfl_up_sync(FULL, Sb, d);
        if (lane >= d){ Sb = Sa*Qb + Sb; Sa = Sa*Qa; }
    }
    if (lane == 31){ sA[wid][0] = Sa; sA[wid][1] = Sb; }
    __syncthreads();
    if (tid == 0){
        double ra = sA[0][0], rb = sA[0][1];
        for (int w = 1; w < NWARP; w++){
            double ca = sA[w][0], cb = sA[w][1];
            rb = ca*rb + cb; ra = ca*ra;
            sA[w][0] = ra; sA[w][1] = rb;
        }
    }
    __syncthreads();

    double Ea = __shfl_up_sync(FULL, Sa, 1);
    double Eb = __shfl_up_sync(FULL, Sb, 1);
    if (lane == 0){ Ea = 1.0; Eb = 0.0; }
    double Wa = 1.0, Wb = 0.0;
    if (wid > 0){ Wa = sA[wid-1][0]; Wb = sA[wid-1][1]; }
    double exa = Ea*Wa, exb = Ea*Wb + Eb;
    double agA = sA[NWARP-1][0], agB = sA[NWARP-1][1];

    if (tid < 32){
        double Pa, Pb;
        lookbackA(tile, lane, agA, agB, &Pa, &Pb);
        if (lane == 0){ sP[0] = Pa; sP[1] = Pb; }
    }
    __syncthreads();

    float f = (float)(exa * sP[1] + exb);

    // likelihood
    double loc = 0.0;
    {
        float Sp = Sp0;
        float tprev = tprev0;
        #pragma unroll
        for (int q = 0; q < PT; q++){
            float nt = s_nt[kloc+q];
            unsigned enc = s_de[kloc+q];
            float dd = __uint_as_float(enc & ~7u);
            float amp = sam[enc & 7u];
            float dt = nt - tprev; tprev = nt;
            float phi = expf(-c*dt);
            float phi2 = phi*phi;
            float V = amp, U = a*V;
            float Am = dd + U*V;
            float S = phi2 * Sp;
            float D = Am - U*U*S;
            float W = (V - U*S) / D;
            float fin = phi * f;
            float z = s_y[kloc+q] - U * fin;
            f = fin + W * z;
            Sp = S + D*W*W;
            loc += (double)(z*z / D) + (double)logf(D);
        }
    }
    sred[tid] = loc;
    __syncthreads();
    for (int off = TPB/2; off > 0; off >>= 1){
        if (tid < off) sred[tid] += sred[tid+off];
        __syncthreads();
    }
    if (tid == 0) g_bsum[tile] = sred[0];
}

__global__ void k_final(float* out){
    __shared__ double red[1024];
    int tid = threadIdx.x;
    double s = g_bsum[tid*2] + g_bsum[tid*2+1];
    red[tid] = s;
    __syncthreads();
    for (int off = 512; off > 0; off >>= 1){
        if (tid < off) red[tid] += red[tid+off];
        __syncthreads();
    }
    if (tid == 0) out[0] = (float)(0.5 * (red[0] + (double)NTOT * 1.8378770664093454));
}

// ---------------- launch ----------------
extern "C" void kernel_launch(void* const* d_in, const int* in_sizes, int n_in,
                              void* d_out, int out_size){
    const float* t    = (const float*)d_in[0];
    const int*   band = (const int*)  d_in[1];
    const float* y    = (const float*)d_in[2];
    const float* dg   = (const float*)d_in[3];
    const float* lad  = (const float*)d_in[4];
    const float* lg   = (const float*)d_in[5];
    const float* lkp  = (const float*)d_in[6];
    float* out = (float*)d_out;

    k_init    <<<1, 32>>>(lad, lg, lkp);
    k_reset   <<<NTILE/256, 256>>>();
    k_count   <<<SC_NBLK, TPB>>>(band);
    k_offsets8<<<NBANDS, TPB>>>();
    k_scatter <<<SC_NBLK, TPB>>>(t, band);

    k_mergeL<<<dim3(2*R_CAP/TILE, 4), TPB>>>(0);
    k_mergeL<<<dim3(4*R_CAP/TILE, 2), TPB>>>(1);

    k_mgsr    <<<NTILE, TPB>>>(y, dg);
    k_blkscanM<<<1, 1024>>>();
    k_apply   <<<NTILE, TPB>>>();
    k_final   <<<1, 1024>>>(out);
}

// round 13
// speedup vs baseline: 1.3573x; 1.3573x over previous
#include <cuda_runtime.h>
#include <stdint.h>
#include <math.h>

#define NTOT    (1<<22)
#define NBANDS  8
#define TPB     256

#define SC_CHUNK 2048
#define SC_NBLK  (NTOT/SC_CHUNK)   /* 2048 */
#define SC_L     (SC_CHUNK/TPB)    /* 8    */

#define R_CAP    540672             /* NTOT/8 + 16384 */

#define TILE     2048
#define NTILE    (NTOT/TILE)        /* 2048 */
#define PT       8                  /* merge kernel: TILE/TPB */

#define WARM     512
#define WIN      (TILE+WARM)        /* 2560 */
#define WPT      (WIN/TPB)          /* 10 */
#define NWARP    (TPB/32)           /* 8 */

typedef unsigned long long ull;

// ---------------- static device scratch ----------------
__device__ ull    g_key[8*R_CAP];
__device__ ull    g_keyB[8*R_CAP];
__device__ int    g_bcnt[NBANDS*SC_NBLK];
__device__ int    g_boff[NBANDS*SC_NBLK];
__device__ int    g_cnt[NBANDS];
__device__ double g_bsum[NTILE];
__device__ float  g_amps[NBANDS], g_lags[NBANDS], g_ka, g_kc;

__device__ __forceinline__ unsigned fkey(float f){
    unsigned u = __float_as_uint(f);
    return (u & 0x80000000u) ? ~u : (u | 0x80000000u);
}
__device__ __forceinline__ float unfkey(unsigned k){
    unsigned u = (k & 0x80000000u) ? (k & 0x7fffffffu) : ~k;
    return __uint_as_float(u);
}

__device__ __forceinline__ void mmulD(double r[4], const double n[4], const double o[4]){
    double t0 = n[0]*o[0] + n[1]*o[2];
    double t1 = n[0]*o[1] + n[1]*o[3];
    double t2 = n[2]*o[0] + n[3]*o[2];
    double t3 = n[2]*o[1] + n[3]*o[3];
    double mx = fmax(fmax(fabs(t0),fabs(t1)), fmax(fabs(t2),fabs(t3)));
    double s  = (mx > 0.0) ? 1.0/mx : 1.0;
    r[0]=t0*s; r[1]=t1*s; r[2]=t2*s; r[3]=t3*s;
}

// ---------------- params ----------------
__global__ void k_init(const float* __restrict__ lad, const float* __restrict__ lg,
                       const float* __restrict__ lkp){
    if (threadIdx.x == 0){
        g_amps[0] = 1.f; g_lags[0] = 0.f;
        for (int b = 1; b < NBANDS; b++){
            g_amps[b] = expf(lad[b-1]);
            g_lags[b] = lg[b-1];
        }
        g_ka = expf(lkp[0]);
        g_kc = expf(lkp[1]);
    }
}

// ---------------- stage 1: histogram (band-major) ----------------
__global__ void k_count(const int* __restrict__ band){
    __shared__ int sc[NBANDS];
    int tid = threadIdx.x;
    if (tid < NBANDS) sc[tid] = 0;
    __syncthreads();
    int cnt[NBANDS];
    #pragma unroll
    for (int b = 0; b < NBANDS; b++) cnt[b] = 0;
    int base = blockIdx.x * SC_CHUNK;
    for (int k = tid; k < SC_CHUNK; k += TPB) cnt[band[base+k]]++;
    #pragma unroll
    for (int b = 0; b < NBANDS; b++) if (cnt[b]) atomicAdd(&sc[b], cnt[b]);
    __syncthreads();
    if (tid < NBANDS) g_bcnt[tid*SC_NBLK + blockIdx.x] = sc[tid];
}

// ---------------- stage 1b: 8 independent per-band scans ----------------
__global__ void k_offsets8(){
    __shared__ int ssum[TPB];
    int b = blockIdx.x;
    int tid = threadIdx.x;
    int v[SC_NBLK/TPB];
    int run = 0;
    #pragma unroll
    for (int q = 0; q < SC_NBLK/TPB; q++){
        v[q] = run;
        run += g_bcnt[b*SC_NBLK + tid*(SC_NBLK/TPB) + q];
    }
    ssum[tid] = run;
    __syncthreads();
    for (int off = 1; off < TPB; off <<= 1){
        int pv = (tid >= off) ? ssum[tid-off] : 0;
        __syncthreads();
        ssum[tid] += pv;
        __syncthreads();
    }
    int excl = tid ? ssum[tid-1] : 0;
    #pragma unroll
    for (int q = 0; q < SC_NBLK/TPB; q++)
        g_boff[b*SC_NBLK + tid*(SC_NBLK/TPB) + q] = excl + v[q];
    if (tid == TPB-1) g_cnt[b] = excl + run;
}

// ---------------- stage 2: stable partition into band regions ----------------
__global__ void k_scatter(const float* __restrict__ t, const int* __restrict__ band){
    __shared__ float s_t[SC_CHUNK];
    __shared__ int   s_b[SC_CHUNK];
    __shared__ int   s_scan[NBANDS*TPB];
    __shared__ float s_lag[NBANDS];
    int tid = threadIdx.x;
    int base = blockIdx.x * SC_CHUNK;
    if (tid < NBANDS) s_lag[tid] = g_lags[tid];
    for (int k = tid; k < SC_CHUNK; k += TPB){
        s_t[k] = t[base+k]; s_b[k] = band[base+k];
    }
    __syncthreads();
    int cnt[NBANDS];
    #pragma unroll
    for (int b = 0; b < NBANDS; b++) cnt[b] = 0;
    #pragma unroll
    for (int j = 0; j < SC_L; j++) cnt[s_b[tid*SC_L + j]]++;
    #pragma unroll
    for (int b = 0; b < NBANDS; b++) s_scan[b*TPB + tid] = cnt[b];
    __syncthreads();
    for (int off = 1; off < TPB; off <<= 1){
        int v[NBANDS];
        #pragma unroll
        for (int b = 0; b < NBANDS; b++) v[b] = (tid >= off) ? s_scan[b*TPB + tid - off] : 0;
        __syncthreads();
        #pragma unroll
        for (int b = 0; b < NBANDS; b++) s_scan[b*TPB + tid] += v[b];
        __syncthreads();
    }
    int pos[NBANDS];
    #pragma unroll
    for (int b = 0; b < NBANDS; b++)
        pos[b] = b*R_CAP + g_boff[b*SC_NBLK + blockIdx.x] + (tid ? s_scan[b*TPB + tid - 1] : 0);
    #pragma unroll
    for (int j = 0; j < SC_L; j++){
        int li = tid*SC_L + j;
        int b = s_b[li];
        float nt = s_t[li] - s_lag[b];
        ull key = ((ull)fkey(nt) << 32) | ((ull)(unsigned)(base + li) << 3) | (unsigned)b;
        g_key[pos[b]++] = key;
    }
}

// ---------------- merge-path helpers ----------------
__device__ __forceinline__ int diag_g(const ull* __restrict__ A, int la,
                                      const ull* __restrict__ B, int lb, int k){
    int lo = k - lb; if (lo < 0) lo = 0;
    int hi = k < la ? k : la;
    while (lo < hi){
        int mid = (lo + hi) >> 1;
        if (__ldg(&A[mid]) < __ldg(&B[k-mid-1])) lo = mid + 1; else hi = mid;
    }
    return lo;
}

__global__ void k_mergeL(int level){
    __shared__ ull sbuf[TILE];
    __shared__ int s_i0, s_i1;
    int p = blockIdx.y;

    const ull* src; ull* dst;
    int aS, bS, dS, la, lb;
    if (level == 0){
        src = g_key; dst = g_keyB;
        aS = (2*p)*R_CAP;   la = g_cnt[2*p];
        bS = (2*p+1)*R_CAP; lb = g_cnt[2*p+1];
        dS = (2*p)*R_CAP;
    } else {
        src = g_keyB; dst = g_key;
        aS = (4*p)*R_CAP;   la = g_cnt[4*p]   + g_cnt[4*p+1];
        bS = (4*p+2)*R_CAP; lb = g_cnt[4*p+2] + g_cnt[4*p+3];
        dS = (4*p)*R_CAP;
    }
    int psize = la + lb;
    int t0 = blockIdx.x * TILE;
    if (t0 >= psize) return;
    int t1 = t0 + TILE; if (t1 > psize) t1 = psize;
    int tsz = t1 - t0;

    const ull* A = src + aS;
    const ull* B = src + bS;

    if (threadIdx.x == 0)  s_i0 = diag_g(A, la, B, lb, t0);
    if (threadIdx.x == 32) s_i1 = diag_g(A, la, B, lb, t1);
    __syncthreads();
    int i0 = s_i0, i1 = s_i1;
    int j0 = t0 - i0;
    int ai = i1 - i0;
    int bj = tsz - ai;

    for (int k = threadIdx.x; k < tsz; k += TPB)
        sbuf[k] = (k < ai) ? A[i0 + k] : B[j0 + k - ai];
    __syncthreads();

    int kloc = threadIdx.x * PT;
    int n = tsz - kloc; if (n > PT) n = PT; if (n < 0) n = 0;
    ull out[PT];
    if (n > 0){
        int lo = kloc - bj; if (lo < 0) lo = 0;
        int hi = kloc < ai ? kloc : ai;
        while (lo < hi){
            int mid = (lo + hi) >> 1;
            if (sbuf[mid] < sbuf[ai + kloc - mid - 1]) lo = mid + 1; else hi = mid;
        }
        int i = lo, j = kloc - lo;
        #pragma unroll
        for (int q = 0; q < PT; q++){
            if (q < n){
                bool ta = (j >= bj) || (i < ai && sbuf[i] < sbuf[ai + j]);
                out[q] = ta ? sbuf[i++] : sbuf[ai + j++];
            }
        }
    }
    __syncthreads();
    #pragma unroll
    for (int q = 0; q < PT; q++) if (q < n) sbuf[kloc + q] = out[q];
    __syncthreads();
    ull* D = dst + dS + t0;
    for (int k = threadIdx.x; k < tsz; k += TPB) D[k] = sbuf[k];
}

// ---------------- fused: merge window + gather + local scans + likelihood ----------------
__global__ void __launch_bounds__(TPB)
k_fused(const float* __restrict__ y, const float* __restrict__ dg){
    __shared__ __align__(16) char raw[WIN*16];   // phase1: ull sbuf (20KB); phase2: 4 arrays (40KB)
    ull*   sbuf = (ull*)raw;
    float* s_nt = (float*)raw;
    float* s_am = (float*)(raw + WIN*4);
    float* s_y  = (float*)(raw + WIN*8);
    float* s_dd = (float*)(raw + WIN*12);
    __shared__ double sWin[NWARP][4];
    __shared__ double sAf[NWARP][2];
    __shared__ double sred[TPB];
    __shared__ float  sam[NBANDS];
    __shared__ int    s_i0, s_i1;
    const unsigned FULL = 0xFFFFFFFFu;

    int tid = threadIdx.x;
    int lane = tid & 31;
    int wid  = tid >> 5;
    if (tid < NBANDS) sam[tid] = g_amps[tid];

    int t0 = blockIdx.x * TILE;
    int gs = t0 - WARM;
    int pad = 0;
    if (gs < 0){ pad = -gs; gs = 0; }
    int g1 = t0 + TILE;
    int realLen = g1 - gs;

    // ---- final 2-list merge of the window ----
    int la = g_cnt[0] + g_cnt[1] + g_cnt[2] + g_cnt[3];
    int lb = NTOT - la;
    const ull* A = g_key;
    const ull* B = g_key + 4*R_CAP;
    if (tid == 0)  s_i0 = diag_g(A, la, B, lb, gs);
    if (tid == 32) s_i1 = diag_g(A, la, B, lb, g1);
    __syncthreads();
    int i0 = s_i0, i1 = s_i1, j0 = gs - i0;
    int aii = i1 - i0, bjj = realLen - aii;
    for (int k = tid; k < realLen; k += TPB)
        sbuf[pad + k] = (k < aii) ? A[i0 + k] : B[j0 + k - aii];
    __syncthreads();

    int kloc = tid * WPT;
    int m0 = kloc - pad; if (m0 < 0) m0 = 0;
    int lo = m0 - bjj; if (lo < 0) lo = 0;
    int hi = m0 < aii ? m0 : aii;
    while (lo < hi){
        int mid = (lo + hi) >> 1;
        if (sbuf[pad + mid] < sbuf[pad + aii + m0 - mid - 1]) lo = mid + 1; else hi = mid;
    }
    int ii = lo, jj = m0 - lo;
    ull out[WPT];
    #pragma unroll
    for (int q = 0; q < WPT; q++){
        if (kloc + q >= pad){
            bool ta = (jj >= bjj) || (ii < aii && sbuf[pad + ii] < sbuf[pad + aii + jj]);
            out[q] = ta ? sbuf[pad + ii++] : sbuf[pad + aii + jj++];
        } else out[q] = 0ULL;
    }
    __syncthreads();   // all sbuf reads done; raw reusable as 4 float arrays

    // ---- decode + gather into smem (pads get identity-sentinel elements) ----
    #pragma unroll
    for (int q = 0; q < WPT; q++){
        int slot = kloc + q;
        if (slot < pad){
            s_nt[slot] = -1e30f;   // sentinel: first real element sees huge dt -> phi=0 (exact reset)
            s_am[slot] = 0.f;      // U=V=0 -> identity matrix, f unchanged
            s_y [slot] = 0.f;
            s_dd[slot] = 1.f;
        } else {
            ull kk = out[q];
            int idx = (int)((kk >> 3) & 0x3FFFFFu);
            s_nt[slot] = unfkey((unsigned)(kk >> 32));
            s_am[slot] = sam[(int)(kk & 7u)];
            s_y [slot] = __ldg(&y[idx]);
            s_dd[slot] = __ldg(&dg[idx]);
        }
    }
    __syncthreads();
    float tprev0 = kloc ? s_nt[kloc-1] : s_nt[0];   // window-first dt = 0 (absorbed by warmup)
    float a = g_ka, c = g_kc;

    // ---- per-thread Mobius segment (fp32) ----
    float m0f=1.f, m1f=0.f, m2f=0.f, m3f=1.f;
    {
        float tprev = tprev0;
        #pragma unroll
        for (int q = 0; q < WPT; q++){
            int slot = kloc + q;
            float nt = s_nt[slot];
            float dd = s_dd[slot];
            float amp = s_am[slot];
            float dt = nt - tprev; tprev = nt;
            float phi2 = expf(-2.f*c*dt);
            float V = amp, U = a*amp;
            float Am = dd + U*V;
            float e00 = (Am - 2.f*U*V)*phi2, e01 = V*V, e10 = -U*U*phi2, e11 = Am;
            float r0 = e00*m0f + e01*m2f, r1 = e00*m1f + e01*m3f;
            float r2 = e10*m0f + e11*m2f, r3 = e10*m1f + e11*m3f;
            float mx = fmaxf(fmaxf(fabsf(r0),fabsf(r1)), fmaxf(fabsf(r2),fabsf(r3)));
            float sc = (mx > 0.f) ? 1.f/mx : 1.f;
            m0f=r0*sc; m1f=r1*sc; m2f=r2*sc; m3f=r3*sc;
        }
    }
    // ---- fp64 warp scan of matrices ----
    double W[4] = {(double)m0f,(double)m1f,(double)m2f,(double)m3f};
    #pragma unroll
    for (int d = 1; d < 32; d <<= 1){
        double Q[4];
        #pragma unroll
        for (int q = 0; q < 4; q++) Q[q] = __shfl_up_sync(FULL, W[q], d);
        if (lane >= d){ double R[4]; mmulD(R, W, Q); W[0]=R[0]; W[1]=R[1]; W[2]=R[2]; W[3]=R[3]; }
    }
    if (lane == 31){ sWin[wid][0]=W[0]; sWin[wid][1]=W[1]; sWin[wid][2]=W[2]; sWin[wid][3]=W[3]; }
    __syncthreads();
    if (tid == 0){
        double run[4] = {sWin[0][0], sWin[0][1], sWin[0][2], sWin[0][3]};
        for (int w = 1; w < NWARP; w++){
            double cu[4] = {sWin[w][0], sWin[w][1], sWin[w][2], sWin[w][3]};
            double r[4]; mmulD(r, cu, run);
            for (int q=0;q<4;q++){ run[q]=r[q]; sWin[w][q]=r[q]; }
        }
    }
    __syncthreads();
    float Sp0;
    {
        double Pd[4];
        #pragma unroll
        for (int q = 0; q < 4; q++) Pd[q] = __shfl_up_sync(FULL, W[q], 1);
        if (lane == 0){ Pd[0]=1.0; Pd[1]=0.0; Pd[2]=0.0; Pd[3]=1.0; }
        double Wd[4];
        if (wid == 0){ Wd[0]=1.0; Wd[1]=0.0; Wd[2]=0.0; Wd[3]=1.0; }
        else { for (int q=0;q<4;q++) Wd[q] = sWin[wid-1][q]; }
        double Ex[4]; mmulD(Ex, Pd, Wd);
        Sp0 = (float)(Ex[1] / Ex[3]);   // window starts at S = 0
    }

    // ---- f-affine per thread + fp64 warp scan (window starts at f = 0) ----
    double Sa, Sb;
    {
        float Sp = Sp0;
        float al = 1.f, be = 0.f;
        float tprev = tprev0;
        #pragma unroll
        for (int q = 0; q < WPT; q++){
            int slot = kloc + q;
            float nt = s_nt[slot];
            float dd = s_dd[slot];
            float amp = s_am[slot];
            float dt = nt - tprev; tprev = nt;
            float phi = expf(-c*dt);
            float phi2 = phi*phi;
            float V = amp, U = a*V;
            float Am = dd + U*V;
            float S = phi2 * Sp;
            float D = Am - U*U*S;
            float Wc = (V - U*S) / D;
            float an = phi * (1.f - Wc*U);
            float bn = Wc * s_y[slot];
            be = an*be + bn;
            al *= an;
            Sp = S + D*Wc*Wc;
        }
        Sa = (double)al; Sb = (double)be;
    }
    #pragma unroll
    for (int d = 1; d < 32; d <<= 1){
        double Qa = __shfl_up_sync(FULL, Sa, d);
        double Qb = __shfl_up_sync(FULL, Sb, d);
        if (lane >= d){ Sb = Sa*Qb + Sb; Sa = Sa*Qa; }
    }
    if (lane == 31){ sAf[wid][0] = Sa; sAf[wid][1] = Sb; }
    __syncthreads();
    if (tid == 0){
        double ra = sAf[0][0], rb = sAf[0][1];
        for (int w = 1; w < NWARP; w++){
            double ca = sAf[w][0], cb = sAf[w][1];
            rb = ca*rb + cb; ra = ca*ra;
            sAf[w][0] = ra; sAf[w][1] = rb;
        }
    }
    __syncthreads();
    float f;
    {
        double Ea = __shfl_up_sync(FULL, Sa, 1);
        double Eb = __shfl_up_sync(FULL, Sb, 1);
        if (lane == 0){ Ea = 1.0; Eb = 0.0; }
        double Wa = 1.0, Wb = 0.0;
        if (wid > 0){ Wa = sAf[wid-1][0]; Wb = sAf[wid-1][1]; }
        f = (float)(Ea*Wb + Eb);   // f0 = 0 -> f = exclusive_b
    }

    // ---- likelihood over tile region (slots >= WARM) ----
    double loc = 0.0;
    {
        float Sp = Sp0;
        float tprev = tprev0;
        #pragma unroll
        for (int q = 0; q < WPT; q++){
            int slot = kloc + q;
            float nt = s_nt[slot];
            float dd = s_dd[slot];
            float amp = s_am[slot];
            float dt = nt - tprev; tprev = nt;
            float phi = expf(-c*dt);
            float phi2 = phi*phi;
            float V = amp, U = a*V;
            float Am = dd + U*V;
            float S = phi2 * Sp;
            float D = Am - U*U*S;
            float Wc = (V - U*S) / D;
            float fin = phi * f;
            float z = s_y[slot] - U * fin;
            f = fin + Wc * z;
            Sp = S + D*Wc*Wc;
            if (slot >= WARM)
                loc += (double)(z*z / D) + (double)logf(D);
        }
    }
    sred[tid] = loc;
    __syncthreads();
    for (int off = TPB/2; off > 0; off >>= 1){
        if (tid < off) sred[tid] += sred[tid+off];
        __syncthreads();
    }
    if (tid == 0) g_bsum[blockIdx.x] = sred[0];
}

__global__ void k_final(float* out){
    __shared__ double red[1024];
    int tid = threadIdx.x;
    double s = g_bsum[tid*2] + g_bsum[tid*2+1];
    red[tid] = s;
    __syncthreads();
    for (int off = 512; off > 0; off >>= 1){
        if (tid < off) red[tid] += red[tid+off];
        __syncthreads();
    }
    if (tid == 0) out[0] = (float)(0.5 * (red[0] + (double)NTOT * 1.8378770664093454));
}

// ---------------- launch ----------------
extern "C" void kernel_launch(void* const* d_in, const int* in_sizes, int n_in,
                              void* d_out, int out_size){
    const float* t    = (const float*)d_in[0];
    const int*   band = (const int*)  d_in[1];
    const float* y    = (const float*)d_in[2];
    const float* dg   = (const float*)d_in[3];
    const float* lad  = (const float*)d_in[4];
    const float* lg   = (const float*)d_in[5];
    const float* lkp  = (const float*)d_in[6];
    float* out = (float*)d_out;

    k_init    <<<1, 32>>>(lad, lg, lkp);
    k_count   <<<SC_NBLK, TPB>>>(band);
    k_offsets8<<<NBANDS, TPB>>>();
    k_scatter <<<SC_NBLK, TPB>>>(t, band);

    k_mergeL<<<dim3(2*R_CAP/TILE, 4), TPB>>>(0);
    k_mergeL<<<dim3(4*R_CAP/TILE, 2), TPB>>>(1);

    k_fused <<<NTILE, TPB>>>(y, dg);
    k_final <<<1, 1024>>>(out);
}